// round 14
// baseline (speedup 1.0000x reference)
#include <cuda_runtime.h>
#include <cuda_bf16.h>
#include <math.h>
#include <stdint.h>

// ---------------- dims ----------------
#define MD 2048
#define NQKV 6144
#define NFF 8192
#define EPS 1e-5f

// ---------------- scratch ----------------
__device__ float g_altx[32 * MD];
__device__ float g_s[32 * MD];
__device__ float g_y[32 * MD];
__device__ float g_imv[32 * MD];
__device__ float g_part[4194304];    // 16 MB partials
__device__ float g_part2[4194304];   // 16 MB partials (fc1 -> fc2)

// ---------------- helpers ----------------
#define SWA(o) ((o) ^ ((((o) >> 7) & 3u) << 4))

__device__ __forceinline__ uint32_t smem_u32(const void* p) {
    uint32_t a;
    asm("{ .reg .u64 t; cvta.to.shared.u64 t, %1; cvt.u32.u64 %0, t; }" : "=r"(a) : "l"(p));
    return a;
}

// cheap split: hi = truncate-to-bf16 (top 16 bits), lo = bf16(f - hi) (truncated)
__device__ __forceinline__ void pack2(float f0, float f1, uint32_t& hi, uint32_t& lo) {
    uint32_t u0 = __float_as_uint(f0), u1 = __float_as_uint(f1);
    float l0 = f0 - __uint_as_float(u0 & 0xffff0000u);
    float l1 = f1 - __uint_as_float(u1 & 0xffff0000u);
    hi = __byte_perm(u0, u1, 0x7632);
    lo = __byte_perm(__float_as_uint(l0), __float_as_uint(l1), 0x7632);
}

#define LDSM4(r0, r1, r2, r3, a) \
    asm volatile("ldmatrix.sync.aligned.m8n8.x4.shared.b16 {%0,%1,%2,%3},[%4];" \
        : "=r"(r0), "=r"(r1), "=r"(r2), "=r"(r3) : "r"(a))

#define MMA16816(d, a0, a1, a2, a3, b0, b1) \
    asm volatile("mma.sync.aligned.m16n8k16.row.col.f32.bf16.bf16.f32 " \
        "{%0,%1,%2,%3},{%4,%5,%6,%7},{%8,%9},{%0,%1,%2,%3};" \
        : "+f"((d)[0]), "+f"((d)[1]), "+f"((d)[2]), "+f"((d)[3]) \
        : "r"(a0), "r"(a1), "r"(a2), "r"(a3), "r"(b0), "r"(b1))

__device__ __forceinline__ float sinbias(int i, int n) {
    int j2 = n & ~1;
    float ang = (float)i * expf(-(float)j2 * (9.210340371976184f / 1024.f));
    return (n & 1) ? cosf(ang) : sinf(ang);
}

__device__ __forceinline__ float gelu_f(float a) {
    return 0.5f * a * (1.f + erff(a * 0.70710678118654752f));
}

// ================ segment average ================
__global__ void avg_k(const float* __restrict__ x, float* __restrict__ altx) {
    int idx = blockIdx.x * 256 + threadIdx.x;
    int i = idx >> 11;
    int m = idx & 2047;
    int c1 = m >> 5;
    int c2 = m & 31;
    const float4* p = (const float4*)(x + ((c2 << 6) + c1) * 2048 + (i << 6));
    float s = 0.f;
#pragma unroll
    for (int t = 0; t < 16; t++) { float4 v = p[t]; s += v.x + v.y + v.z + v.w; }
    altx[idx] = s * (1.f / 64.f);
}

// ================ bf16-split GEMM, sync-free mainloop (R12 design) ================
// D[256 W-rows x 32 tokens] per CTA; warp w: rows [w*32, w*32+32).
// B k-slice preloaded ONCE to smem as bf16 hi/lo; K loop has zero syncs.
// ks1=0: B = X[tok][k].   ks1>0 (fc2): B = gelu(sum_{sp<ks1} X[sp*32K + tok*K + k] + bias[k]).
#define MAXNCH 8

__global__ __launch_bounds__(256, 2) void gemm_mma(
    const float* __restrict__ X, const float* __restrict__ W,
    float* __restrict__ P, int N, int K, int kc, int ks1,
    const float* __restrict__ bias)
{
    __shared__ __align__(16) union SU {
        char b[MAXNCH * 4096];
        float ep[32 * 260];
    } sm;

    int tid = threadIdx.x;
    int wid = tid >> 5, lane = tid & 31;

    int rowq = lane >> 2;
    int kpo = 2 * (lane & 3);
    const float* A0 = W + ((size_t)blockIdx.x * 256 + wid * 32 + rowq) * K + kpo;
    size_t rK8 = (size_t)8 * K;

    int k0 = blockIdx.y * kc;
    int NCH = kc >> 5;
    int NST = NCH * 2;

    // ---- A prologue ----
    float2 af[8];
    {
        const float* Ab = A0 + k0;
#pragma unroll
        for (int mt = 0; mt < 2; mt++) {
            const float* Am = Ab + (size_t)mt * 16 * K;
            af[mt * 4 + 0] = *(const float2*)(Am);
            af[mt * 4 + 1] = *(const float2*)(Am + rK8);
            af[mt * 4 + 2] = *(const float2*)(Am + 8);
            af[mt * 4 + 3] = *(const float2*)(Am + rK8 + 8);
        }
    }

    // ---- B phase ----
    {
        int btok = tid >> 3, bkf = (tid & 7) * 4;
        uint32_t blocal = SWA((uint32_t)(btok * 64 + bkf * 2));
        for (int c = 0; c < NCH; c++) {
            int kg = k0 + c * 32 + bkf;
            float4 b4;
            if (ks1 == 0) {
                b4 = *(const float4*)&X[(size_t)btok * K + kg];
            } else {
                const float* pp = X + (size_t)btok * K + kg;
                size_t sps = (size_t)32 * K;
                b4 = make_float4(0.f, 0.f, 0.f, 0.f);
                for (int sp = 0; sp < ks1; sp++) {
                    float4 q = *(const float4*)&pp[sp * sps];
                    b4.x += q.x; b4.y += q.y; b4.z += q.z; b4.w += q.w;
                }
                float4 bb = *(const float4*)&bias[kg];
                b4.x = gelu_f(b4.x + bb.x);
                b4.y = gelu_f(b4.y + bb.y);
                b4.z = gelu_f(b4.z + bb.z);
                b4.w = gelu_f(b4.w + bb.w);
            }
            uint2 hi, lo;
            pack2(b4.x, b4.y, hi.x, lo.x);
            pack2(b4.z, b4.w, hi.y, lo.y);
            *(uint2*)(sm.b + c * 4096 + blocal) = hi;
            *(uint2*)(sm.b + c * 4096 + 2048 + blocal) = lo;
        }
    }
    __syncthreads();

    float d[2][4][4];
#pragma unroll
    for (int mt = 0; mt < 2; mt++)
#pragma unroll
        for (int f = 0; f < 4; f++)
#pragma unroll
            for (int i = 0; i < 4; i++) d[mt][f][i] = 0.f;

    uint32_t sb = smem_u32(&sm);
    uint32_t b_tokoff = (uint32_t)(((lane >> 4) * 8 + (lane & 7)) * 64);
    uint32_t b_kb = (uint32_t)(((lane >> 3) & 1) * 16);

    // ---- sync-free mainloop ----
    for (int ch = 0; ch < NCH; ch++) {
        uint32_t bhB = sb + (uint32_t)(ch * 4096);
        uint32_t blB = bhB + 2048;
#pragma unroll
        for (int kk = 0; kk < 2; kk++) {
            int st = ch * 2 + kk;
            uint32_t ah[2][4], al[2][4];
#pragma unroll
            for (int mt = 0; mt < 2; mt++)
#pragma unroll
                for (int j = 0; j < 4; j++)
                    pack2(af[mt * 4 + j].x, af[mt * 4 + j].y, ah[mt][j], al[mt][j]);
            if (st + 1 < NST) {
                const float* An = A0 + k0 + (st + 1) * 16;
#pragma unroll
                for (int mt = 0; mt < 2; mt++) {
                    const float* Am = An + (size_t)mt * 16 * K;
                    af[mt * 4 + 0] = *(const float2*)(Am);
                    af[mt * 4 + 1] = *(const float2*)(Am + rK8);
                    af[mt * 4 + 2] = *(const float2*)(Am + 8);
                    af[mt * 4 + 3] = *(const float2*)(Am + rK8 + 8);
                }
            }
            uint32_t bh[8], bl[8];
#pragma unroll
            for (int g = 0; g < 2; g++) {
                uint32_t bo = SWA((uint32_t)(g * 16 * 64) + b_tokoff + b_kb + (uint32_t)(kk * 32));
                LDSM4(bh[g * 4 + 0], bh[g * 4 + 1], bh[g * 4 + 2], bh[g * 4 + 3], bhB + bo);
                LDSM4(bl[g * 4 + 0], bl[g * 4 + 1], bl[g * 4 + 2], bl[g * 4 + 3], blB + bo);
            }
#pragma unroll
            for (int mt = 0; mt < 2; mt++)
#pragma unroll
                for (int f = 0; f < 4; f++)
                    MMA16816(d[mt][f], ah[mt][0], ah[mt][1], ah[mt][2], ah[mt][3],
                             bh[f * 2], bh[f * 2 + 1]);
#pragma unroll
            for (int mt = 0; mt < 2; mt++)
#pragma unroll
                for (int f = 0; f < 4; f++)
                    MMA16816(d[mt][f], ah[mt][0], ah[mt][1], ah[mt][2], ah[mt][3],
                             bl[f * 2], bl[f * 2 + 1]);
#pragma unroll
            for (int mt = 0; mt < 2; mt++)
#pragma unroll
                for (int f = 0; f < 4; f++)
                    MMA16816(d[mt][f], al[mt][0], al[mt][1], al[mt][2], al[mt][3],
                             bh[f * 2], bh[f * 2 + 1]);
        }
    }
    __syncthreads();

    // ---- epilogue ----
#pragma unroll
    for (int mt = 0; mt < 2; mt++)
#pragma unroll
        for (int f = 0; f < 4; f++)
#pragma unroll
            for (int i = 0; i < 4; i++) {
                int m = wid * 32 + mt * 16 + (lane >> 2) + ((i >> 1) << 3);
                int tok = f * 8 + (lane & 3) * 2 + (i & 1);
                sm.ep[tok * 260 + m] = d[mt][f][i];
            }
    __syncthreads();
    {
        size_t pb = (size_t)blockIdx.y * 32 * N + (size_t)blockIdx.x * 256;
        for (int e = tid; e < 8192; e += 256) {
            int tok = e >> 8, col = e & 255;
            P[pb + (size_t)tok * N + col] = sm.ep[tok * 260 + col];
        }
    }
}

// ================ LN stat helper ================
__device__ __forceinline__ void ln_stats(float sum, float sq, float* red, int tid,
                                         float& mu, float& rstd) {
    int w = tid >> 5, lane = tid & 31;
#pragma unroll
    for (int off = 16; off; off >>= 1) {
        sum += __shfl_xor_sync(0xffffffffu, sum, off);
        sq  += __shfl_xor_sync(0xffffffffu, sq, off);
    }
    if (lane == 0) { red[w] = sum; red[32 + w] = sq; }
    __syncthreads();
    if (tid == 0) {
        float a = 0.f, b = 0.f;
        for (int k = 0; k < 8; k++) { a += red[k]; b += red[32 + k]; }
        red[60] = a; red[61] = b;
    }
    __syncthreads();
    mu = red[60] * (1.f / 2048.f);
    float var = red[61] * (1.f / 2048.f) - mu * mu;
    rstd = rsqrtf(var + EPS);
}

// ================ fused epilogues ================
__global__ void postA_k(const float* __restrict__ P, float* __restrict__ s,
                        float* __restrict__ y, const float* __restrict__ g,
                        const float* __restrict__ bt, int ks)
{
    __shared__ float red[64];
    int i = blockIdx.x, tid = threadIdx.x;
    float v[8]; float sum = 0.f, sq = 0.f;
#pragma unroll
    for (int j = 0; j < 8; j++) {
        int n = tid + j * 256;
        float a = 0.f;
        for (int sp = 0; sp < ks; sp++) a += P[(size_t)sp * 65536 + i * 2048 + n];
        a += sinbias(i, n);
        v[j] = a; s[i * 2048 + n] = a; sum += a; sq += a * a;
    }
    float mu, rstd;
    ln_stats(sum, sq, red, tid, mu, rstd);
#pragma unroll
    for (int j = 0; j < 8; j++) {
        int n = tid + j * 256;
        y[i * 2048 + n] = (v[j] - mu) * rstd * g[n] + bt[n];
    }
}

__global__ void postB_k(const float* __restrict__ P, float* __restrict__ s,
                        const float* __restrict__ g, const float* __restrict__ bt, int ks)
{
    __shared__ float red[64];
    int i = blockIdx.x, tid = threadIdx.x;
    float v[8]; float sum = 0.f, sq = 0.f;
#pragma unroll
    for (int j = 0; j < 8; j++) {
        int n = tid + j * 256;
        float a = 0.f;
        for (int sp = 0; sp < ks; sp++) a += P[(size_t)sp * 65536 + i * 2048 + n];
        a += s[i * 2048 + n];
        v[j] = a; sum += a; sq += a * a;
    }
    float mu, rstd;
    ln_stats(sum, sq, red, tid, mu, rstd);
#pragma unroll
    for (int j = 0; j < 8; j++) {
        int n = tid + j * 256;
        s[i * 2048 + n] = (v[j] - mu) * rstd * g[n] + bt[n] + v[j];
    }
}

__global__ void postD_k(const float* __restrict__ P, float* __restrict__ s,
                        float* __restrict__ y, const float* __restrict__ bias,
                        const float* __restrict__ g, const float* __restrict__ bt,
                        float* __restrict__ out, int last, int ks)
{
    __shared__ float red[64];
    int i = blockIdx.x, tid = threadIdx.x;
    float v[8]; float sum = 0.f, sq = 0.f;
#pragma unroll
    for (int j = 0; j < 8; j++) {
        int n = tid + j * 256;
        float a = 0.f;
        for (int sp = 0; sp < ks; sp++) a += P[(size_t)sp * 65536 + i * 2048 + n];
        a += bias[n];
        v[j] = a; sum += a; sq += a * a;
    }
    if (last) {
#pragma unroll
        for (int j = 0; j < 8; j++) out[i * 2048 + tid + j * 256] = v[j];
        return;
    }
    float mu, rstd;
    ln_stats(sum, sq, red, tid, mu, rstd);
#pragma unroll
    for (int j = 0; j < 8; j++) {
        int n = tid + j * 256;
        s[i * 2048 + n] = v[j];
        y[i * 2048 + n] = (v[j] - mu) * rstd * g[n] + bt[n];
    }
}

// ================ scalar attention + cumsum (fused qkv split-K sum) ================
__global__ void attn_k(const float* __restrict__ P, float* __restrict__ imv, int ks) {
    const size_t ST = (size_t)32 * 6144;
    int h = blockIdx.x;
    int tid = threadIdx.x;
    int w = tid >> 5, lane = tid & 31;
    __shared__ float rsa[32];

#pragma unroll
    for (int ii = 0; ii < 8; ii++) {
        int i = w * 8 + ii;
        size_t qb = (size_t)i * 6144 + h * 128 + lane * 4;
        float4 qa = make_float4(0.f, 0.f, 0.f, 0.f), ka = make_float4(0.f, 0.f, 0.f, 0.f);
        for (int sp = 0; sp < ks; sp++) {
            float4 q = *(const float4*)&P[sp * ST + qb];
            float4 k = *(const float4*)&P[sp * ST + qb + 2048];
            qa.x += q.x; qa.y += q.y; qa.z += q.z; qa.w += q.w;
            ka.x += k.x; ka.y += k.y; ka.z += k.z; ka.w += k.w;
        }
        float p = qa.x * ka.x + qa.y * ka.y + qa.z * ka.z + qa.w * ka.w;
#pragma unroll
        for (int off = 16; off; off >>= 1) p += __shfl_xor_sync(0xffffffffu, p, off);
        if (lane == 0) rsa[i] = p * 0.08838834764831845f;
    }
    __syncthreads();

    int d = tid;
    float run = 0.f;
#pragma unroll
    for (int i = 0; i < 32; i++) {
        size_t vb = (size_t)i * 6144 + 4096 + h * 128 + d;
        float vv = 0.f;
        for (int sp = 0; sp < ks; sp++) vv += P[sp * ST + vb];
        run += rsa[i] * vv;
        imv[i * 2048 + h * 128 + d] = run;
    }
}

// ================ launch ================
extern "C" void kernel_launch(void* const* d_in, const int* in_sizes, int n_in,
                              void* d_out, int out_size)
{
    const float* x      = (const float*)d_in[0];
    const float* weight = (const float*)d_in[1];
    const float* Wqkv   = (const float*)d_in[2];
    const float* Wo     = (const float*)d_in[3];
    const float* ln1_g  = (const float*)d_in[4];
    const float* ln1_b  = (const float*)d_in[5];
    const float* ln2_g  = (const float*)d_in[6];
    const float* ln2_b  = (const float*)d_in[7];
    const float* fc1_w  = (const float*)d_in[8];
    const float* fc1_b  = (const float*)d_in[9];
    const float* fc2_w  = (const float*)d_in[10];
    const float* fc2_b  = (const float*)d_in[11];
    float* out = (float*)d_out;

    float *p_altx, *p_s, *p_y, *p_imv, *p_part, *p_part2;
    cudaGetSymbolAddress((void**)&p_altx, g_altx);
    cudaGetSymbolAddress((void**)&p_s,    g_s);
    cudaGetSymbolAddress((void**)&p_y,    g_y);
    cudaGetSymbolAddress((void**)&p_imv,  g_imv);
    cudaGetSymbolAddress((void**)&p_part, g_part);
    cudaGetSymbolAddress((void**)&p_part2, g_part2);

    avg_k<<<256, 256>>>(x, p_altx);

    // s = weight @ altx^T + sinbias ; y = LN1(s)   (N=2048, ks=32, kc=64 -> grid 256)
    gemm_mma<<<dim3(8, 32), 256>>>(p_altx, weight, p_part, MD, MD, 64, 0, nullptr);
    postA_k<<<32, 256>>>(p_part, p_s, p_y, ln1_g, ln1_b, 32);

    for (int a = 0; a < 3; a++) {
        // qkv   (N=6144, ks=16, kc=128 -> grid 384)
        gemm_mma<<<dim3(24, 16), 256>>>(p_y, Wqkv + (size_t)a * NQKV * MD,
                                        p_part, NQKV, MD, 128, 0, nullptr);
        attn_k<<<16, 128>>>(p_part, p_imv, 16);

        // Wo    (N=2048, ks=32, kc=64 -> grid 256)
        gemm_mma<<<dim3(8, 32), 256>>>(p_imv, Wo + (size_t)a * MD * MD,
                                       p_part, MD, MD, 64, 0, nullptr);
        postB_k<<<32, 256>>>(p_part, p_s, ln2_g, ln2_b, 32);

        // fc1   (N=8192, ks=16, kc=128 -> grid 512) -> part2
        gemm_mma<<<dim3(32, 16), 256>>>(p_s, fc1_w, p_part2, NFF, MD, 128, 0, nullptr);

        // fc2   (N=2048, K=8192, ks=64, kc=128 -> grid 512); B = gelu(reduce16(part2)+fc1_b)
        gemm_mma<<<dim3(8, 64), 256>>>(p_part2, fc2_w, p_part, MD, NFF, 128, 16, fc1_b);
        postD_k<<<32, 256>>>(p_part, p_s, p_y, fc2_b, ln1_g, ln1_b, out, a == 2, 64);
    }
}

// round 15
// speedup vs baseline: 1.3690x; 1.3690x over previous
#include <cuda_runtime.h>
#include <cuda_bf16.h>
#include <math.h>
#include <stdint.h>

// ---------------- dims ----------------
#define MD 2048
#define NQKV 6144
#define NFF 8192
#define EPS 1e-5f

// ---------------- scratch ----------------
__device__ float g_altx[32 * MD];
__device__ float g_s[32 * MD];
__device__ float g_y[32 * MD];
__device__ float g_imv[32 * MD];
__device__ float g_qkv[32 * NQKV];
__device__ float g_part[2097152];    // 8 MB partials
__device__ float g_part2[2097152];   // 8 MB partials (fc1 -> fc2)

// ---------------- helpers ----------------
__device__ __forceinline__ uint32_t smem_u32(const void* p) {
    uint32_t a;
    asm("{ .reg .u64 t; cvta.to.shared.u64 t, %1; cvt.u32.u64 %0, t; }" : "=r"(a) : "l"(p));
    return a;
}

__device__ __forceinline__ uint32_t cvt_tf32(float f) {
    uint32_t r;
    asm("cvt.rna.tf32.f32 %0, %1;" : "=r"(r) : "f"(f));
    return r;
}

#define LDS32(r, a) \
    asm volatile("ld.shared.b32 %0,[%1];" : "=r"(r) : "r"(a))

#define MMATF32(d, a0, a1, a2, a3, b0, b1) \
    asm volatile("mma.sync.aligned.m16n8k8.row.col.f32.tf32.tf32.f32 " \
        "{%0,%1,%2,%3},{%4,%5,%6,%7},{%8,%9},{%0,%1,%2,%3};" \
        : "+f"((d)[0]), "+f"((d)[1]), "+f"((d)[2]), "+f"((d)[3]) \
        : "r"(a0), "r"(a1), "r"(a2), "r"(a3), "r"(b0), "r"(b1))

__device__ __forceinline__ float sinbias(int i, int n) {
    int j2 = n & ~1;
    float ang = (float)i * expf(-(float)j2 * (9.210340371976184f / 1024.f));
    return (n & 1) ? cosf(ang) : sinf(ang);
}

__device__ __forceinline__ float gelu_f(float a) {
    return 0.5f * a * (1.f + erff(a * 0.70710678118654752f));
}

// ================ segment average ================
__global__ void avg_k(const float* __restrict__ x, float* __restrict__ altx) {
    int idx = blockIdx.x * 256 + threadIdx.x;
    int i = idx >> 11;
    int m = idx & 2047;
    int c1 = m >> 5;
    int c2 = m & 31;
    const float4* p = (const float4*)(x + ((c2 << 6) + c1) * 2048 + (i << 6));
    float s = 0.f;
#pragma unroll
    for (int t = 0; t < 16; t++) { float4 v = p[t]; s += v.x + v.y + v.z + v.w; }
    altx[idx] = s * (1.f / 64.f);
}

// ================ single-tf32 GEMM (mma.sync m16n8k8), sync-free mainloop ============
// D[256 W-rows x 32 tokens] per CTA; warp w: rows [w*32, w*32+32).
// A: direct LDG.32 fragments (fp32 -> cvt.rna tf32), double-buffered in regs.
// B: whole k-slice preloaded once to smem as tf32, layout [k16-chunk][tok(pitch 20w)][16k].
// ks1=0: B = X[tok][k].  ks1>0 (fc2): B = gelu(sum_{sp<ks1} X[...] + bias[k]).
// Partials out: P[split][token][row_global].
#define BCH 2560                 // bytes per 16-k chunk (32 tok x 20 words)
#define MAXCH16 16

struct StepA { float v[16]; };

__global__ __launch_bounds__(256, 2) void gemm_mma(
    const float* __restrict__ X, const float* __restrict__ W,
    float* __restrict__ P, int N, int K, int kc, int ks1,
    const float* __restrict__ bias)
{
    __shared__ __align__(16) union SU {
        char b[MAXCH16 * BCH];    // 40960 B
        float ep[32 * 260];
    } sm;

    int tid = threadIdx.x;
    int wid = tid >> 5, lane = tid & 31;
    int rowq = lane >> 2;
    int kq = lane & 3;

    int k0 = blockIdx.y * kc;
    int NST = kc >> 4;            // k16 steps

    // A base: row (bx*256 + wid*32 + rowq), k offset kq
    const float* A0 = W + ((size_t)blockIdx.x * 256 + wid * 32 + rowq) * K + k0 + kq;
    size_t r8K = (size_t)8 * K;
    size_t r16K = (size_t)16 * K;

    // ---- B phase: load/convert entire k-slice into smem (tf32 bits) ----
    {
        int btok = tid >> 3, bkf = (tid & 7) * 4;   // bkf in {0..28}
        int NC32 = kc >> 5;
        uint32_t wbase = (uint32_t)(btok * 20 + (bkf & 15));
        for (int c = 0; c < NC32; c++) {
            int kg = k0 + c * 32 + bkf;
            float4 b4;
            if (ks1 == 0) {
                b4 = *(const float4*)&X[(size_t)btok * K + kg];
            } else {
                const float* pp = X + (size_t)btok * K + kg;
                size_t sps = (size_t)32 * K;
                b4 = make_float4(0.f, 0.f, 0.f, 0.f);
                for (int sp = 0; sp < ks1; sp++) {
                    float4 q = *(const float4*)&pp[sp * sps];
                    b4.x += q.x; b4.y += q.y; b4.z += q.z; b4.w += q.w;
                }
                float4 bb = *(const float4*)&bias[kg];
                b4.x = gelu_f(b4.x + bb.x);
                b4.y = gelu_f(b4.y + bb.y);
                b4.z = gelu_f(b4.z + bb.z);
                b4.w = gelu_f(b4.w + bb.w);
            }
            uint4 t;
            t.x = cvt_tf32(b4.x); t.y = cvt_tf32(b4.y);
            t.z = cvt_tf32(b4.z); t.w = cvt_tf32(b4.w);
            int ch16 = c * 2 + (bkf >> 4);
            *(uint4*)((float*)sm.b + ch16 * 640 + wbase) = t;
        }
    }

    // ---- A prologue: step 0 fragments ----
    float afA[16], afB[16];
    {
        const float* Ab = A0;
#pragma unroll
        for (int mt = 0; mt < 2; mt++)
#pragma unroll
            for (int kh = 0; kh < 2; kh++) {
                const float* Am = Ab + mt * r16K + kh * 8;
                int j = mt * 8 + kh * 4;
                afA[j + 0] = Am[0];
                afA[j + 1] = Am[r8K];
                afA[j + 2] = Am[4];
                afA[j + 3] = Am[r8K + 4];
            }
    }
    __syncthreads();   // B visibility

    float d[2][4][4];
#pragma unroll
    for (int mt = 0; mt < 2; mt++)
#pragma unroll
        for (int f = 0; f < 4; f++)
#pragma unroll
            for (int i = 0; i < 4; i++) d[mt][f][i] = 0.f;

    uint32_t sb = smem_u32(&sm);
    uint32_t bl_base = sb + (uint32_t)(rowq * 80 + kq * 4);

    // ---- mainloop: unroll by 2 with register double-buffer ----
#define STEP_BODY(CUR, NXT, ST) do { \
    uint32_t au[16]; \
    _Pragma("unroll") \
    for (int j = 0; j < 16; j++) au[j] = cvt_tf32((CUR)[j]); \
    if ((ST) + 1 < NST) { \
        const float* An = A0 + ((ST) + 1) * 16; \
        _Pragma("unroll") \
        for (int mt = 0; mt < 2; mt++) \
        _Pragma("unroll") \
        for (int kh = 0; kh < 2; kh++) { \
            const float* Am = An + mt * r16K + kh * 8; \
            int j = mt * 8 + kh * 4; \
            (NXT)[j + 0] = Am[0]; \
            (NXT)[j + 1] = Am[r8K]; \
            (NXT)[j + 2] = Am[4]; \
            (NXT)[j + 3] = Am[r8K + 4]; \
        } \
    } \
    uint32_t bW = bl_base + (uint32_t)((ST) * BCH); \
    _Pragma("unroll") \
    for (int kh = 0; kh < 2; kh++) { \
        uint32_t b0[4], b1[4]; \
        _Pragma("unroll") \
        for (int g = 0; g < 4; g++) { \
            uint32_t ad = bW + (uint32_t)(g * 640 + kh * 32); \
            LDS32(b0[g], ad); \
            LDS32(b1[g], ad + 16); \
        } \
        _Pragma("unroll") \
        for (int mt = 0; mt < 2; mt++) { \
            int j = mt * 8 + kh * 4; \
            _Pragma("unroll") \
            for (int g = 0; g < 4; g++) \
                MMATF32(d[mt][g], au[j], au[j + 1], au[j + 2], au[j + 3], b0[g], b1[g]); \
        } \
    } \
} while (0)

    for (int st = 0; st < NST; st += 2) {
        STEP_BODY(afA, afB, st);
        STEP_BODY(afB, afA, st + 1);
    }
#undef STEP_BODY
    __syncthreads();

    // ---- epilogue: transpose via smem (pitch 260 floats) ----
#pragma unroll
    for (int mt = 0; mt < 2; mt++)
#pragma unroll
        for (int f = 0; f < 4; f++)
#pragma unroll
            for (int i = 0; i < 4; i++) {
                int m = wid * 32 + mt * 16 + (lane >> 2) + ((i >> 1) << 3);
                int tok = f * 8 + (lane & 3) * 2 + (i & 1);
                sm.ep[tok * 260 + m] = d[mt][f][i];
            }
    __syncthreads();
    {
        size_t pb = (size_t)blockIdx.y * 32 * N + (size_t)blockIdx.x * 256;
        for (int e = tid; e < 8192; e += 256) {
            int tok = e >> 8, col = e & 255;
            P[pb + (size_t)tok * N + col] = sm.ep[tok * 260 + col];
        }
    }
}

// ================ LN stat helper ================
__device__ __forceinline__ void ln_stats(float sum, float sq, float* red, int tid,
                                         float& mu, float& rstd) {
    int w = tid >> 5, lane = tid & 31;
#pragma unroll
    for (int off = 16; off; off >>= 1) {
        sum += __shfl_xor_sync(0xffffffffu, sum, off);
        sq  += __shfl_xor_sync(0xffffffffu, sq, off);
    }
    if (lane == 0) { red[w] = sum; red[32 + w] = sq; }
    __syncthreads();
    if (tid == 0) {
        float a = 0.f, b = 0.f;
        for (int k = 0; k < 8; k++) { a += red[k]; b += red[32 + k]; }
        red[60] = a; red[61] = b;
    }
    __syncthreads();
    mu = red[60] * (1.f / 2048.f);
    float var = red[61] * (1.f / 2048.f) - mu * mu;
    rstd = rsqrtf(var + EPS);
}

// ================ fused epilogues ================
__global__ void postA_k(const float* __restrict__ P, float* __restrict__ s,
                        float* __restrict__ y, const float* __restrict__ g,
                        const float* __restrict__ bt, int ks)
{
    __shared__ float red[64];
    int i = blockIdx.x, tid = threadIdx.x;
    float v[8]; float sum = 0.f, sq = 0.f;
#pragma unroll
    for (int j = 0; j < 8; j++) {
        int n = tid + j * 256;
        float a = 0.f;
        for (int sp = 0; sp < ks; sp++) a += P[(size_t)sp * 65536 + i * 2048 + n];
        a += sinbias(i, n);
        v[j] = a; s[i * 2048 + n] = a; sum += a; sq += a * a;
    }
    float mu, rstd;
    ln_stats(sum, sq, red, tid, mu, rstd);
#pragma unroll
    for (int j = 0; j < 8; j++) {
        int n = tid + j * 256;
        y[i * 2048 + n] = (v[j] - mu) * rstd * g[n] + bt[n];
    }
}

__global__ void postB_k(const float* __restrict__ P, float* __restrict__ s,
                        const float* __restrict__ g, const float* __restrict__ bt, int ks)
{
    __shared__ float red[64];
    int i = blockIdx.x, tid = threadIdx.x;
    float v[8]; float sum = 0.f, sq = 0.f;
#pragma unroll
    for (int j = 0; j < 8; j++) {
        int n = tid + j * 256;
        float a = 0.f;
        for (int sp = 0; sp < ks; sp++) a += P[(size_t)sp * 65536 + i * 2048 + n];
        a += s[i * 2048 + n];
        v[j] = a; sum += a; sq += a * a;
    }
    float mu, rstd;
    ln_stats(sum, sq, red, tid, mu, rstd);
#pragma unroll
    for (int j = 0; j < 8; j++) {
        int n = tid + j * 256;
        s[i * 2048 + n] = (v[j] - mu) * rstd * g[n] + bt[n] + v[j];
    }
}

__global__ void postD_k(const float* __restrict__ P, float* __restrict__ s,
                        float* __restrict__ y, const float* __restrict__ bias,
                        const float* __restrict__ g, const float* __restrict__ bt,
                        float* __restrict__ out, int last, int ks)
{
    __shared__ float red[64];
    int i = blockIdx.x, tid = threadIdx.x;
    float v[8]; float sum = 0.f, sq = 0.f;
#pragma unroll
    for (int j = 0; j < 8; j++) {
        int n = tid + j * 256;
        float a = 0.f;
        for (int sp = 0; sp < ks; sp++) a += P[(size_t)sp * 65536 + i * 2048 + n];
        a += bias[n];
        v[j] = a; sum += a; sq += a * a;
    }
    if (last) {
#pragma unroll
        for (int j = 0; j < 8; j++) out[i * 2048 + tid + j * 256] = v[j];
        return;
    }
    float mu, rstd;
    ln_stats(sum, sq, red, tid, mu, rstd);
#pragma unroll
    for (int j = 0; j < 8; j++) {
        int n = tid + j * 256;
        s[i * 2048 + n] = v[j];
        y[i * 2048 + n] = (v[j] - mu) * rstd * g[n] + bt[n];
    }
}

// ================ dense reduce of qkv partials (full-grid, float4) ================
__global__ void reduceq_k(const float* __restrict__ P, float* __restrict__ q, int ks) {
    int i = blockIdx.x * 256 + threadIdx.x;    // float4 index over 32*6144/4 = 49152
    const float4* P4 = (const float4*)P;
    float4 a = make_float4(0.f, 0.f, 0.f, 0.f);
    for (int sp = 0; sp < ks; sp++) {
        float4 v = P4[(size_t)sp * 49152 + i];
        a.x += v.x; a.y += v.y; a.z += v.z; a.w += v.w;
    }
    ((float4*)q)[i] = a;
}

// ================ scalar attention + cumsum on dense qkv ================
__global__ void attn_k(const float* __restrict__ Q, float* __restrict__ imv) {
    int h = blockIdx.x;
    int tid = threadIdx.x;
    int w = tid >> 5, lane = tid & 31;
    __shared__ float rsa[32];

#pragma unroll
    for (int ii = 0; ii < 8; ii++) {
        int i = w * 8 + ii;
        size_t qb = (size_t)i * 6144 + h * 128 + lane * 4;
        float4 qa = *(const float4*)&Q[qb];
        float4 ka = *(const float4*)&Q[qb + 2048];
        float p = qa.x * ka.x + qa.y * ka.y + qa.z * ka.z + qa.w * ka.w;
#pragma unroll
        for (int off = 16; off; off >>= 1) p += __shfl_xor_sync(0xffffffffu, p, off);
        if (lane == 0) rsa[i] = p * 0.08838834764831845f;
    }
    __syncthreads();

    int d = tid;
    float run = 0.f;
#pragma unroll
    for (int i = 0; i < 32; i++) {
        run += rsa[i] * Q[(size_t)i * 6144 + 4096 + h * 128 + d];
        imv[i * 2048 + h * 128 + d] = run;
    }
}

// ================ launch ================
extern "C" void kernel_launch(void* const* d_in, const int* in_sizes, int n_in,
                              void* d_out, int out_size)
{
    const float* x      = (const float*)d_in[0];
    const float* weight = (const float*)d_in[1];
    const float* Wqkv   = (const float*)d_in[2];
    const float* Wo     = (const float*)d_in[3];
    const float* ln1_g  = (const float*)d_in[4];
    const float* ln1_b  = (const float*)d_in[5];
    const float* ln2_g  = (const float*)d_in[6];
    const float* ln2_b  = (const float*)d_in[7];
    const float* fc1_w  = (const float*)d_in[8];
    const float* fc1_b  = (const float*)d_in[9];
    const float* fc2_w  = (const float*)d_in[10];
    const float* fc2_b  = (const float*)d_in[11];
    float* out = (float*)d_out;

    float *p_altx, *p_s, *p_y, *p_imv, *p_qkv, *p_part, *p_part2;
    cudaGetSymbolAddress((void**)&p_altx, g_altx);
    cudaGetSymbolAddress((void**)&p_s,    g_s);
    cudaGetSymbolAddress((void**)&p_y,    g_y);
    cudaGetSymbolAddress((void**)&p_imv,  g_imv);
    cudaGetSymbolAddress((void**)&p_qkv,  g_qkv);
    cudaGetSymbolAddress((void**)&p_part, g_part);
    cudaGetSymbolAddress((void**)&p_part2, g_part2);

    avg_k<<<256, 256>>>(x, p_altx);

    // s = weight @ altx^T + sinbias ; y = LN1(s)   (N=2048, ks=16, kc=128)
    gemm_mma<<<dim3(8, 16), 256>>>(p_altx, weight, p_part, MD, MD, 128, 0, nullptr);
    postA_k<<<32, 256>>>(p_part, p_s, p_y, ln1_g, ln1_b, 16);

    for (int a = 0; a < 3; a++) {
        // qkv   (N=6144, ks=8, kc=256)
        gemm_mma<<<dim3(24, 8), 256>>>(p_y, Wqkv + (size_t)a * NQKV * MD,
                                       p_part, NQKV, MD, 256, 0, nullptr);
        reduceq_k<<<192, 256>>>(p_part, p_qkv, 8);
        attn_k<<<16, 128>>>(p_qkv, p_imv);

        // Wo    (N=2048, ks=16, kc=128)
        gemm_mma<<<dim3(8, 16), 256>>>(p_imv, Wo + (size_t)a * MD * MD,
                                       p_part, MD, MD, 128, 0, nullptr);
        postB_k<<<32, 256>>>(p_part, p_s, ln2_g, ln2_b, 16);

        // fc1   (N=8192, ks=8, kc=256) -> part2
        gemm_mma<<<dim3(32, 8), 256>>>(p_s, fc1_w, p_part2, NFF, MD, 256, 0, nullptr);

        // fc2   (N=2048, K=8192, ks=32, kc=256); B = gelu(reduce8(part2)+fc1_b) fused
        gemm_mma<<<dim3(8, 32), 256>>>(p_part2, fc2_w, p_part, MD, NFF, 256, 8, fc1_b);
        postD_k<<<32, 256>>>(p_part, p_s, p_y, fc2_b, ln1_g, ln1_b, out, a == 2, 32);
    }
}

// round 16
// speedup vs baseline: 2.1071x; 1.5392x over previous
#include <cuda_runtime.h>
#include <cuda_bf16.h>
#include <math.h>
#include <stdint.h>

// ---------------- dims ----------------
#define MD 2048
#define NQKV 6144
#define NFF 8192
#define EPS 1e-5f

// ---------------- scratch ----------------
__device__ float g_altx[32 * MD];
__device__ float g_s[32 * MD];
__device__ float g_y[32 * MD];
__device__ float g_imv[32 * MD];
__device__ float g_qkv[32 * NQKV];
__device__ float g_part[2097152];    // 8 MB partials
__device__ float g_part2[2097152];   // 8 MB partials (fc1 -> fc2)

// ---------------- helpers ----------------
#define SWA(o) ((o) ^ ((((o) >> 7) & 3u) << 4))

__device__ __forceinline__ uint32_t smem_u32(const void* p) {
    uint32_t a;
    asm("{ .reg .u64 t; cvta.to.shared.u64 t, %1; cvt.u32.u64 %0, t; }" : "=r"(a) : "l"(p));
    return a;
}

// cheap split: hi = truncate-to-bf16 (top 16 bits), lo = bf16(f - hi) (truncated)
__device__ __forceinline__ void pack2(float f0, float f1, uint32_t& hi, uint32_t& lo) {
    uint32_t u0 = __float_as_uint(f0), u1 = __float_as_uint(f1);
    float l0 = f0 - __uint_as_float(u0 & 0xffff0000u);
    float l1 = f1 - __uint_as_float(u1 & 0xffff0000u);
    hi = __byte_perm(u0, u1, 0x7632);
    lo = __byte_perm(__float_as_uint(l0), __float_as_uint(l1), 0x7632);
}

#define LDSM4(r0, r1, r2, r3, a) \
    asm volatile("ldmatrix.sync.aligned.m8n8.x4.shared.b16 {%0,%1,%2,%3},[%4];" \
        : "=r"(r0), "=r"(r1), "=r"(r2), "=r"(r3) : "r"(a))

#define MMA16816(d, a0, a1, a2, a3, b0, b1) \
    asm volatile("mma.sync.aligned.m16n8k16.row.col.f32.bf16.bf16.f32 " \
        "{%0,%1,%2,%3},{%4,%5,%6,%7},{%8,%9},{%0,%1,%2,%3};" \
        : "+f"((d)[0]), "+f"((d)[1]), "+f"((d)[2]), "+f"((d)[3]) \
        : "r"(a0), "r"(a1), "r"(a2), "r"(a3), "r"(b0), "r"(b1))

__device__ __forceinline__ float sinbias(int i, int n) {
    int j2 = n & ~1;
    float ang = (float)i * expf(-(float)j2 * (9.210340371976184f / 1024.f));
    return (n & 1) ? cosf(ang) : sinf(ang);
}

__device__ __forceinline__ float gelu_f(float a) {
    return 0.5f * a * (1.f + erff(a * 0.70710678118654752f));
}

// ================ segment average ================
__global__ void avg_k(const float* __restrict__ x, float* __restrict__ altx) {
    int idx = blockIdx.x * 256 + threadIdx.x;
    int i = idx >> 11;
    int m = idx & 2047;
    int c1 = m >> 5;
    int c2 = m & 31;
    const float4* p = (const float4*)(x + ((c2 << 6) + c1) * 2048 + (i << 6));
    float s = 0.f;
#pragma unroll
    for (int t = 0; t < 16; t++) { float4 v = p[t]; s += v.x + v.y + v.z + v.w; }
    altx[idx] = s * (1.f / 64.f);
}

// ================ bf16-split GEMM, sync-free mainloop (R12, proven) ================
// D[256 W-rows x 32 tokens] per CTA; warp w: rows [w*32, w*32+32).
// mode 0: B = X[tok][k].  mode 1 (fc2): B = gelu(sum_{sp<8} X[sp*32K + tok*K + k] + bias[k]).
#define MAXNCH 8

__global__ __launch_bounds__(256, 2) void gemm_mma(
    const float* __restrict__ X, const float* __restrict__ W,
    float* __restrict__ P, int N, int K, int kc, int mode,
    const float* __restrict__ bias)
{
    __shared__ __align__(16) union SU {
        char b[MAXNCH * 4096];
        float ep[32 * 260];
    } sm;

    int tid = threadIdx.x;
    int wid = tid >> 5, lane = tid & 31;

    int rowq = lane >> 2;
    int kpo = 2 * (lane & 3);
    const float* A0 = W + ((size_t)blockIdx.x * 256 + wid * 32 + rowq) * K + kpo;
    size_t rK8 = (size_t)8 * K;

    int k0 = blockIdx.y * kc;
    int NCH = kc >> 5;
    int NST = NCH * 2;

    // ---- A prologue ----
    float2 af[8];
    {
        const float* Ab = A0 + k0;
#pragma unroll
        for (int mt = 0; mt < 2; mt++) {
            const float* Am = Ab + (size_t)mt * 16 * K;
            af[mt * 4 + 0] = *(const float2*)(Am);
            af[mt * 4 + 1] = *(const float2*)(Am + rK8);
            af[mt * 4 + 2] = *(const float2*)(Am + 8);
            af[mt * 4 + 3] = *(const float2*)(Am + rK8 + 8);
        }
    }

    // ---- B phase ----
    {
        int btok = tid >> 3, bkf = (tid & 7) * 4;
        uint32_t blocal = SWA((uint32_t)(btok * 64 + bkf * 2));
        for (int c = 0; c < NCH; c++) {
            int kg = k0 + c * 32 + bkf;
            float4 b4;
            if (mode == 0) {
                b4 = *(const float4*)&X[(size_t)btok * K + kg];
            } else {
                const float* pp = X + (size_t)btok * K + kg;
                size_t sps = (size_t)32 * K;
                b4 = make_float4(0.f, 0.f, 0.f, 0.f);
#pragma unroll
                for (int sp = 0; sp < 8; sp++) {
                    float4 q = *(const float4*)&pp[sp * sps];
                    b4.x += q.x; b4.y += q.y; b4.z += q.z; b4.w += q.w;
                }
                float4 bb = *(const float4*)&bias[kg];
                b4.x = gelu_f(b4.x + bb.x);
                b4.y = gelu_f(b4.y + bb.y);
                b4.z = gelu_f(b4.z + bb.z);
                b4.w = gelu_f(b4.w + bb.w);
            }
            uint2 hi, lo;
            pack2(b4.x, b4.y, hi.x, lo.x);
            pack2(b4.z, b4.w, hi.y, lo.y);
            *(uint2*)(sm.b + c * 4096 + blocal) = hi;
            *(uint2*)(sm.b + c * 4096 + 2048 + blocal) = lo;
        }
    }
    __syncthreads();

    float d[2][4][4];
#pragma unroll
    for (int mt = 0; mt < 2; mt++)
#pragma unroll
        for (int f = 0; f < 4; f++)
#pragma unroll
            for (int i = 0; i < 4; i++) d[mt][f][i] = 0.f;

    uint32_t sb = smem_u32(&sm);
    uint32_t b_tokoff = (uint32_t)(((lane >> 4) * 8 + (lane & 7)) * 64);
    uint32_t b_kb = (uint32_t)(((lane >> 3) & 1) * 16);

    // ---- sync-free mainloop ----
    for (int ch = 0; ch < NCH; ch++) {
        uint32_t bhB = sb + (uint32_t)(ch * 4096);
        uint32_t blB = bhB + 2048;
#pragma unroll
        for (int kk = 0; kk < 2; kk++) {
            int st = ch * 2 + kk;
            uint32_t ah[2][4], al[2][4];
#pragma unroll
            for (int mt = 0; mt < 2; mt++)
#pragma unroll
                for (int j = 0; j < 4; j++)
                    pack2(af[mt * 4 + j].x, af[mt * 4 + j].y, ah[mt][j], al[mt][j]);
            if (st + 1 < NST) {
                const float* An = A0 + k0 + (st + 1) * 16;
#pragma unroll
                for (int mt = 0; mt < 2; mt++) {
                    const float* Am = An + (size_t)mt * 16 * K;
                    af[mt * 4 + 0] = *(const float2*)(Am);
                    af[mt * 4 + 1] = *(const float2*)(Am + rK8);
                    af[mt * 4 + 2] = *(const float2*)(Am + 8);
                    af[mt * 4 + 3] = *(const float2*)(Am + rK8 + 8);
                }
            }
            uint32_t bh[8], bl[8];
#pragma unroll
            for (int g = 0; g < 2; g++) {
                uint32_t bo = SWA((uint32_t)(g * 16 * 64) + b_tokoff + b_kb + (uint32_t)(kk * 32));
                LDSM4(bh[g * 4 + 0], bh[g * 4 + 1], bh[g * 4 + 2], bh[g * 4 + 3], bhB + bo);
                LDSM4(bl[g * 4 + 0], bl[g * 4 + 1], bl[g * 4 + 2], bl[g * 4 + 3], blB + bo);
            }
#pragma unroll
            for (int mt = 0; mt < 2; mt++)
#pragma unroll
                for (int f = 0; f < 4; f++)
                    MMA16816(d[mt][f], ah[mt][0], ah[mt][1], ah[mt][2], ah[mt][3],
                             bh[f * 2], bh[f * 2 + 1]);
#pragma unroll
            for (int mt = 0; mt < 2; mt++)
#pragma unroll
                for (int f = 0; f < 4; f++)
                    MMA16816(d[mt][f], ah[mt][0], ah[mt][1], ah[mt][2], ah[mt][3],
                             bl[f * 2], bl[f * 2 + 1]);
#pragma unroll
            for (int mt = 0; mt < 2; mt++)
#pragma unroll
                for (int f = 0; f < 4; f++)
                    MMA16816(d[mt][f], al[mt][0], al[mt][1], al[mt][2], al[mt][3],
                             bh[f * 2], bh[f * 2 + 1]);
        }
    }
    __syncthreads();

    // ---- epilogue ----
#pragma unroll
    for (int mt = 0; mt < 2; mt++)
#pragma unroll
        for (int f = 0; f < 4; f++)
#pragma unroll
            for (int i = 0; i < 4; i++) {
                int m = wid * 32 + mt * 16 + (lane >> 2) + ((i >> 1) << 3);
                int tok = f * 8 + (lane & 3) * 2 + (i & 1);
                sm.ep[tok * 260 + m] = d[mt][f][i];
            }
    __syncthreads();
    {
        size_t pb = (size_t)blockIdx.y * 32 * N + (size_t)blockIdx.x * 256;
        for (int e = tid; e < 8192; e += 256) {
            int tok = e >> 8, col = e & 255;
            P[pb + (size_t)tok * N + col] = sm.ep[tok * 260 + col];
        }
    }
}

// ================ LN stat helper (512 threads) ================
__device__ __forceinline__ void ln_stats512(float sum, float sq, float* red, int tid,
                                            float& mu, float& rstd) {
    int w = tid >> 5, lane = tid & 31;
#pragma unroll
    for (int off = 16; off; off >>= 1) {
        sum += __shfl_xor_sync(0xffffffffu, sum, off);
        sq  += __shfl_xor_sync(0xffffffffu, sq, off);
    }
    if (lane == 0) { red[w] = sum; red[32 + w] = sq; }
    __syncthreads();
    if (tid == 0) {
        float a = 0.f, b = 0.f;
#pragma unroll
        for (int k = 0; k < 16; k++) { a += red[k]; b += red[32 + k]; }
        red[60] = a; red[61] = b;
    }
    __syncthreads();
    mu = red[60] * (1.f / 2048.f);
    float var = red[61] * (1.f / 2048.f) - mu * mu;
    rstd = rsqrtf(var + EPS);
}

// ================ fused epilogues (templated KS, unrolled split-K, 512 thr) =========
template <int KS>
__global__ void postA_k(const float* __restrict__ P, float* __restrict__ s,
                        float* __restrict__ y, const float* __restrict__ g,
                        const float* __restrict__ bt)
{
    __shared__ float red[64];
    int i = blockIdx.x, tid = threadIdx.x;
    float v[4]; float sum = 0.f, sq = 0.f;
#pragma unroll
    for (int j = 0; j < 4; j++) {
        int n = tid + j * 512;
        float a = 0.f;
#pragma unroll
        for (int sp = 0; sp < KS; sp++) a += P[(size_t)sp * 65536 + i * 2048 + n];
        a += sinbias(i, n);
        v[j] = a; s[i * 2048 + n] = a; sum += a; sq += a * a;
    }
    float mu, rstd;
    ln_stats512(sum, sq, red, tid, mu, rstd);
#pragma unroll
    for (int j = 0; j < 4; j++) {
        int n = tid + j * 512;
        y[i * 2048 + n] = (v[j] - mu) * rstd * g[n] + bt[n];
    }
}

template <int KS>
__global__ void postB_k(const float* __restrict__ P, float* __restrict__ s,
                        const float* __restrict__ g, const float* __restrict__ bt)
{
    __shared__ float red[64];
    int i = blockIdx.x, tid = threadIdx.x;
    float v[4]; float sum = 0.f, sq = 0.f;
#pragma unroll
    for (int j = 0; j < 4; j++) {
        int n = tid + j * 512;
        float a = 0.f;
#pragma unroll
        for (int sp = 0; sp < KS; sp++) a += P[(size_t)sp * 65536 + i * 2048 + n];
        a += s[i * 2048 + n];
        v[j] = a; sum += a; sq += a * a;
    }
    float mu, rstd;
    ln_stats512(sum, sq, red, tid, mu, rstd);
#pragma unroll
    for (int j = 0; j < 4; j++) {
        int n = tid + j * 512;
        s[i * 2048 + n] = (v[j] - mu) * rstd * g[n] + bt[n] + v[j];
    }
}

template <int KS>
__global__ void postD_k(const float* __restrict__ P, float* __restrict__ s,
                        float* __restrict__ y, const float* __restrict__ bias,
                        const float* __restrict__ g, const float* __restrict__ bt,
                        float* __restrict__ out, int last)
{
    __shared__ float red[64];
    int i = blockIdx.x, tid = threadIdx.x;
    float v[4]; float sum = 0.f, sq = 0.f;
#pragma unroll
    for (int j = 0; j < 4; j++) {
        int n = tid + j * 512;
        float a = 0.f;
#pragma unroll
        for (int sp = 0; sp < KS; sp++) a += P[(size_t)sp * 65536 + i * 2048 + n];
        a += bias[n];
        v[j] = a; sum += a; sq += a * a;
    }
    if (last) {
#pragma unroll
        for (int j = 0; j < 4; j++) out[i * 2048 + tid + j * 512] = v[j];
        return;
    }
    float mu, rstd;
    ln_stats512(sum, sq, red, tid, mu, rstd);
#pragma unroll
    for (int j = 0; j < 4; j++) {
        int n = tid + j * 512;
        s[i * 2048 + n] = v[j];
        y[i * 2048 + n] = (v[j] - mu) * rstd * g[n] + bt[n];
    }
}

// ================ dense reduce of qkv partials (templated, unrolled) ================
template <int KS>
__global__ void reduceq_k(const float* __restrict__ P, float* __restrict__ q) {
    int i = blockIdx.x * 256 + threadIdx.x;    // float4 index over 49152
    const float4* P4 = (const float4*)P;
    float4 a = make_float4(0.f, 0.f, 0.f, 0.f);
#pragma unroll
    for (int sp = 0; sp < KS; sp++) {
        float4 v = P4[(size_t)sp * 49152 + i];
        a.x += v.x; a.y += v.y; a.z += v.z; a.w += v.w;
    }
    ((float4*)q)[i] = a;
}

// ================ scalar attention + cumsum on dense qkv ================
__global__ void attn_k(const float* __restrict__ Q, float* __restrict__ imv) {
    int h = blockIdx.x;
    int tid = threadIdx.x;
    int w = tid >> 5, lane = tid & 31;
    __shared__ float rsa[32];

#pragma unroll
    for (int ii = 0; ii < 8; ii++) {
        int i = w * 8 + ii;
        size_t qb = (size_t)i * 6144 + h * 128 + lane * 4;
        float4 qa = *(const float4*)&Q[qb];
        float4 ka = *(const float4*)&Q[qb + 2048];
        float p = qa.x * ka.x + qa.y * ka.y + qa.z * ka.z + qa.w * ka.w;
#pragma unroll
        for (int off = 16; off; off >>= 1) p += __shfl_xor_sync(0xffffffffu, p, off);
        if (lane == 0) rsa[i] = p * 0.08838834764831845f;
    }
    __syncthreads();

    int d = tid;
    float run = 0.f;
#pragma unroll
    for (int i = 0; i < 32; i++) {
        run += rsa[i] * Q[(size_t)i * 6144 + 4096 + h * 128 + d];
        imv[i * 2048 + h * 128 + d] = run;
    }
}

// ================ launch ================
extern "C" void kernel_launch(void* const* d_in, const int* in_sizes, int n_in,
                              void* d_out, int out_size)
{
    const float* x      = (const float*)d_in[0];
    const float* weight = (const float*)d_in[1];
    const float* Wqkv   = (const float*)d_in[2];
    const float* Wo     = (const float*)d_in[3];
    const float* ln1_g  = (const float*)d_in[4];
    const float* ln1_b  = (const float*)d_in[5];
    const float* ln2_g  = (const float*)d_in[6];
    const float* ln2_b  = (const float*)d_in[7];
    const float* fc1_w  = (const float*)d_in[8];
    const float* fc1_b  = (const float*)d_in[9];
    const float* fc2_w  = (const float*)d_in[10];
    const float* fc2_b  = (const float*)d_in[11];
    float* out = (float*)d_out;

    float *p_altx, *p_s, *p_y, *p_imv, *p_qkv, *p_part, *p_part2;
    cudaGetSymbolAddress((void**)&p_altx, g_altx);
    cudaGetSymbolAddress((void**)&p_s,    g_s);
    cudaGetSymbolAddress((void**)&p_y,    g_y);
    cudaGetSymbolAddress((void**)&p_imv,  g_imv);
    cudaGetSymbolAddress((void**)&p_qkv,  g_qkv);
    cudaGetSymbolAddress((void**)&p_part, g_part);
    cudaGetSymbolAddress((void**)&p_part2, g_part2);

    avg_k<<<256, 256>>>(x, p_altx);

    // s = weight @ altx^T + sinbias ; y = LN1(s)   (N=2048, ks=16, kc=128)
    gemm_mma<<<dim3(8, 16), 256>>>(p_altx, weight, p_part, MD, MD, 128, 0, nullptr);
    postA_k<16><<<32, 512>>>(p_part, p_s, p_y, ln1_g, ln1_b);

    for (int a = 0; a < 3; a++) {
        // qkv   (N=6144, ks=8, kc=256)
        gemm_mma<<<dim3(24, 8), 256>>>(p_y, Wqkv + (size_t)a * NQKV * MD,
                                       p_part, NQKV, MD, 256, 0, nullptr);
        reduceq_k<8><<<192, 256>>>(p_part, p_qkv);
        attn_k<<<16, 128>>>(p_qkv, p_imv);

        // Wo    (N=2048, ks=16, kc=128)
        gemm_mma<<<dim3(8, 16), 256>>>(p_imv, Wo + (size_t)a * MD * MD,
                                       p_part, MD, MD, 128, 0, nullptr);
        postB_k<16><<<32, 512>>>(p_part, p_s, ln2_g, ln2_b);

        // fc1   (N=8192, ks=8, kc=256) -> part2
        gemm_mma<<<dim3(32, 8), 256>>>(p_s, fc1_w, p_part2, NFF, MD, 256, 0, nullptr);

        // fc2   (N=2048, K=8192, ks=32, kc=256); B = gelu(reduce8(part2)+fc1_b) fused
        gemm_mma<<<dim3(8, 32), 256>>>(p_part2, fc2_w, p_part, MD, NFF, 256, 1, fc1_b);
        postD_k<32><<<32, 512>>>(p_part, p_s, p_y, fc2_b, ln1_g, ln1_b, out, a == 2);
    }
}